// round 2
// baseline (speedup 1.0000x reference)
#include <cuda_runtime.h>
#include <cstdint>

// Problem constants
#define BATCH 8
#define CCH   128   // channels
#define HH    128
#define WW    256
#define KS    9
#define PADK  4
#define NTOT  (BATCH*CCH*HH*WW)   // 33554432

// Scratch buffer for transposed layout [B, C, W, H]
__device__ float g_tmp[NTOT];

// ---------------------------------------------------------------------------
// Step kernel: buffer layout [B, C, S, L], scan along S, conv along L (contig).
// out[b,co,s_cur,l] = buf[b,co,s_cur,l] + relu( sum_{ci,k} w[co,ci,k] *
//                                                carry[b,ci,s_prev,l+k-4] )
// In-place: row s_cur holds x (this pass hasn't written it yet), row s_prev is
// the finalized previous output. Each element written by exactly one thread.
// ---------------------------------------------------------------------------
template<int CO, int LT, int TCO, int TL, int CIC, int S, int L>
__global__ void __launch_bounds__((CO/TCO)*(LT/TL))
step_kernel(float* __restrict__ buf, const float* __restrict__ wgt,
            int s_cur, int s_prev)
{
    constexpr int NT  = (CO/TCO)*(LT/TL);
    constexpr int CLS = LT + 8;            // csm row stride (floats), 16B-mult
    constexpr int CIS = CO + 4;            // wsm ci stride (floats), 16B-mult
    constexpr int KST = CIC*CIS + 4;       // wsm k stride, 16B-mult, !=0 mod 32

    extern __shared__ float sm[];
    float* csm = sm;                       // [C][CLS]  carry tile (+halo 4 each side)
    float* wsm = sm + CCH*CLS;             // [KS][CIC][CO] padded

    const int b   = blockIdx.z;
    const int co0 = blockIdx.y * CO;
    const int l0  = blockIdx.x * LT;
    const int tid = threadIdx.x;

    float* base = buf + (size_t)b * CCH * S * L;

    // ---- load carry tile (row s_prev), with zero padding at L edges ----
    {
        const float* src = base + (size_t)s_prev * L;
        for (int idx = tid; idx < CCH*CLS; idx += NT) {
            int ci = idx / CLS;
            int j  = idx % CLS;
            int gl = l0 + j - PADK;
            float v = 0.0f;
            if (gl >= 0 && gl < L) v = src[(size_t)ci * S * L + gl];
            csm[idx] = v;
        }
    }

    float acc[TCO][TL];
#pragma unroll
    for (int a = 0; a < TCO; ++a)
#pragma unroll
        for (int j = 0; j < TL; ++j) acc[a][j] = 0.0f;

    const int cog  = tid / (LT/TL);
    const int lg   = tid % (LT/TL);
    const int lofs = lg  * TL;
    const int cofs = cog * TCO;

    for (int ci0 = 0; ci0 < CCH; ci0 += CIC) {
        __syncthreads();   // csm ready (first iter) / wsm free for reuse
        // ---- load weight chunk: wgt[co0+co][ci0+ci][k] -> wsm[k][ci][co] ----
        // idx order: k fastest, then ci, then co -> coalesced global reads
        for (int idx = tid; idx < CO*CIC*KS; idx += NT) {
            int co = idx / (CIC*KS);
            int r  = idx % (CIC*KS);
            int ci = r / KS;
            int k  = r % KS;
            wsm[k*KST + ci*CIS + co] =
                wgt[(size_t)(co0+co)*CCH*KS + (size_t)(ci0+ci)*KS + k];
        }
        __syncthreads();

#pragma unroll 2
        for (int ci = 0; ci < CIC; ++ci) {
            const float* crow = &csm[(ci0+ci)*CLS + lofs];
            float cf[TL+8];
#pragma unroll
            for (int j = 0; j < TL+8; j += 4) {
                float4 v = *(const float4*)(crow + j);
                cf[j] = v.x; cf[j+1] = v.y; cf[j+2] = v.z; cf[j+3] = v.w;
            }
#pragma unroll
            for (int k = 0; k < KS; ++k) {
                const float* wp = &wsm[k*KST + ci*CIS + cofs];
                float wf[TCO];
                if constexpr (TCO == 4) {
                    float4 wv = *(const float4*)wp;
                    wf[0]=wv.x; wf[1]=wv.y; wf[2]=wv.z; wf[3]=wv.w;
                } else if constexpr (TCO == 2) {
                    float2 wv = *(const float2*)wp;
                    wf[0]=wv.x; wf[1]=wv.y;
                } else {
                    wf[0] = *wp;
                }
#pragma unroll
                for (int a = 0; a < TCO; ++a)
#pragma unroll
                    for (int j = 0; j < TL; ++j)
                        acc[a][j] = fmaf(wf[a], cf[j+k], acc[a][j]);
            }
        }
    }

    // ---- epilogue: out = x + relu(conv) ----
#pragma unroll
    for (int a = 0; a < TCO; ++a) {
        float* row = base + ((size_t)(co0+cofs+a) * S + s_cur) * L + l0 + lofs;
        static_assert(TL == 4, "epilogue assumes TL==4");
        float4 xv = *(float4*)row;
        xv.x += fmaxf(acc[a][0], 0.0f);
        xv.y += fmaxf(acc[a][1], 0.0f);
        xv.z += fmaxf(acc[a][2], 0.0f);
        xv.w += fmaxf(acc[a][3], 0.0f);
        *(float4*)row = xv;
    }
}

// ---------------------------------------------------------------------------
// Transpose [P, A, B] -> [P, B, A] (per-plane 2D transpose), A,B mult of 32
// ---------------------------------------------------------------------------
__global__ void transpose_kernel(const float* __restrict__ in,
                                 float* __restrict__ out, int A, int B)
{
    __shared__ float tile[32][33];
    const size_t p = blockIdx.z;
    const int b0 = blockIdx.x * 32;
    const int a0 = blockIdx.y * 32;
    const int tx = threadIdx.x, ty = threadIdx.y;
    const float* ip = in  + p * (size_t)A * B;
    float*       op = out + p * (size_t)A * B;
#pragma unroll
    for (int i = ty; i < 32; i += 8)
        tile[i][tx] = ip[(size_t)(a0+i)*B + (b0+tx)];
    __syncthreads();
#pragma unroll
    for (int i = ty; i < 32; i += 8)
        op[(size_t)(b0+i)*A + (a0+tx)] = tile[tx][i];
}

// Vertical:   layout [B,C,H=128,W=256], scan S=H, conv L=W
using StepV_t = void(*)(float*, const float*, int, int);
#define STEPV step_kernel<32,64,2,4,32,128,256>   // 256 threads, grid (4,4,8)
#define STEPH step_kernel<32,32,2,4,32,256,128>   // 128 threads, grid (4,4,8)

static constexpr int SMEM_V = (CCH*(64+8) + KS*(32*(32+4)+4)) * 4;  // 78480 B
static constexpr int SMEM_H = (CCH*(32+8) + KS*(32*(32+4)+4)) * 4;  // 62096 B

extern "C" void kernel_launch(void* const* d_in, const int* in_sizes, int n_in,
                              void* d_out, int out_size)
{
    const float* x    = (const float*)d_in[0];
    const float* w_ud = (const float*)d_in[1];
    const float* w_du = (const float*)d_in[2];
    const float* w_lr = (const float*)d_in[3];
    const float* w_rl = (const float*)d_in[4];
    float* buf = (float*)d_out;

    float* tbuf = nullptr;
    cudaGetSymbolAddress((void**)&tbuf, g_tmp);

    cudaFuncSetAttribute(STEPV, cudaFuncAttributeMaxDynamicSharedMemorySize, SMEM_V);
    cudaFuncSetAttribute(STEPH, cudaFuncAttributeMaxDynamicSharedMemorySize, SMEM_H);

    // buf <- x (passes run in-place on buf)
    cudaMemcpyAsync(buf, x, (size_t)NTOT * sizeof(float),
                    cudaMemcpyDeviceToDevice, 0);

    // Pass 1: up->down (scan H forward)
    dim3 gv(WW/64, CCH/32, BATCH);      // (4,4,8) = 128 blocks
    for (int h = 1; h < HH; ++h)
        STEPV<<<gv, 256, SMEM_V>>>(buf, w_ud, h, h-1);

    // Pass 2: down->up (scan H backward)
    for (int h = HH-2; h >= 0; --h)
        STEPV<<<gv, 256, SMEM_V>>>(buf, w_du, h, h+1);

    // Transpose [B,C,H,W] -> [B,C,W,H]
    transpose_kernel<<<dim3(WW/32, HH/32, BATCH*CCH), dim3(32,8)>>>(buf, tbuf, HH, WW);

    // Pass 3: left->right (scan W forward in transposed layout)
    dim3 gh(HH/32, CCH/32, BATCH);      // (4,4,8) = 128 blocks
    for (int s = 1; s < WW; ++s)
        STEPH<<<gh, 128, SMEM_H>>>(tbuf, w_lr, s, s-1);

    // Pass 4: right->left (scan W backward)
    for (int s = WW-2; s >= 0; --s)
        STEPH<<<gh, 128, SMEM_H>>>(tbuf, w_rl, s, s+1);

    // Transpose back [B,C,W,H] -> [B,C,H,W]
    transpose_kernel<<<dim3(HH/32, WW/32, BATCH*CCH), dim3(32,8)>>>(tbuf, buf, WW, HH);
}

// round 3
// speedup vs baseline: 3.6112x; 3.6112x over previous
#include <cuda_runtime.h>
#include <cstdint>

#define BATCH 8
#define CCH   128
#define HH    128
#define WW    256
#define KS    9
#define PADK  4
#define NTOT  (BATCH*CCH*HH*WW)

// Scratch buffer for transposed layout [B, C, W, H]
__device__ float g_tmp[NTOT];
// Grid-barrier counters, one per pass (reset each kernel_launch via memset)
__device__ unsigned g_ctr[4];

__device__ __forceinline__ unsigned ld_acq(const unsigned* p) {
    unsigned v;
    asm volatile("ld.acquire.gpu.global.u32 %0, [%1];" : "=r"(v) : "l"(p) : "memory");
    return v;
}
__device__ __forceinline__ void red_rel_add1(unsigned* p) {
    asm volatile("red.release.gpu.global.add.u32 [%0], 1;" :: "l"(p) : "memory");
}

// ---------------------------------------------------------------------------
// Persistent pass kernel. Buffer layout [B, C, S, L]; scan S, conv along L.
// Each block owns (b, co-slice CO, l-tile LT). Block's weights live in smem
// for the whole pass. Steps separated by a counter grid barrier (all blocks
// resident: 128 blocks, 1/SM).
// out[b,co,s,l] = buf[b,co,s,l] + relu( sum_{ci,k} w[co,ci,k]*prev[ci,l+k-4] )
// ---------------------------------------------------------------------------
template<int CO, int LT, int TCO, int TL, int S, int L, int NT>
__global__ void __launch_bounds__(NT)
pass_kernel(float* __restrict__ buf, const float* __restrict__ wgt,
            unsigned* __restrict__ ctr, int reverse)
{
    constexpr int CLS = LT + 8;            // carry row stride (halo 4+4)
    constexpr int CIS = CO + 4;            // wsm ci stride
    constexpr int KST = CCH*CIS + 4;       // wsm k stride

    extern __shared__ float sm[];
    float* csm = sm;                       // [CCH][CLS]
    float* wsm = sm + CCH*CLS;             // [KS][CCH][CO] padded

    const int b   = blockIdx.z;
    const int co0 = blockIdx.y * CO;
    const int l0  = blockIdx.x * LT;
    const int tid = threadIdx.x;
    const unsigned NB = gridDim.x * gridDim.y * gridDim.z;

    float* base = buf + (size_t)b * CCH * S * L;

    // ---- load this block's weight slice once: wgt[co][ci][k] -> wsm[k][ci][co]
    for (int idx = tid; idx < CO*CCH*KS; idx += NT) {
        int co = idx / (CCH*KS);
        int r  = idx % (CCH*KS);
        int ci = r / KS;
        int k  = r % KS;
        wsm[k*KST + ci*CIS + co] =
            wgt[(size_t)(co0+co)*CCH*KS + (size_t)ci*KS + k];
    }

    const int cog  = tid / (LT/TL);
    const int lg   = tid % (LT/TL);
    const int lofs = lg  * TL;
    const int cofs = cog * TCO;

    for (int i = 1; i < S; ++i) {
        const int s_cur  = reverse ? (S-1-i) : i;
        const int s_prev = reverse ? (s_cur+1) : (s_cur-1);

        // ---- carry tile: previous finalized row, all 128 ci, with L-edge pad
        {
            const float* src = base + (size_t)s_prev * L;
            for (int idx = tid; idx < CCH*CLS; idx += NT) {
                int ci = idx / CLS;
                int j  = idx % CLS;
                int gl = l0 + j - PADK;
                float v = 0.0f;
                if (gl >= 0 && gl < L) v = src[(size_t)ci * S * L + gl];
                csm[idx] = v;
            }
        }
        __syncthreads();   // csm (and on i==1, wsm) ready

        float acc[TCO][TL];
#pragma unroll
        for (int a = 0; a < TCO; ++a)
#pragma unroll
            for (int j = 0; j < TL; ++j) acc[a][j] = 0.0f;

#pragma unroll 2
        for (int ci = 0; ci < CCH; ++ci) {
            const float* crow = &csm[ci*CLS + lofs];
            float cf[TL+8];
            if constexpr ((TL & 3) == 0) {
#pragma unroll
                for (int j = 0; j < TL+8; j += 4) {
                    float4 v = *(const float4*)(crow + j);
                    cf[j]=v.x; cf[j+1]=v.y; cf[j+2]=v.z; cf[j+3]=v.w;
                }
            } else {
#pragma unroll
                for (int j = 0; j < TL+8; j += 2) {
                    float2 v = *(const float2*)(crow + j);
                    cf[j]=v.x; cf[j+1]=v.y;
                }
            }
#pragma unroll
            for (int k = 0; k < KS; ++k) {
                const float* wp = &wsm[k*KST + ci*CIS + cofs];
                float wf[TCO];
                static_assert(TCO == 2, "weight load assumes TCO==2");
                float2 wv = *(const float2*)wp;
                wf[0]=wv.x; wf[1]=wv.y;
#pragma unroll
                for (int a = 0; a < TCO; ++a)
#pragma unroll
                    for (int j = 0; j < TL; ++j)
                        acc[a][j] = fmaf(wf[a], cf[j+k], acc[a][j]);
            }
        }

        // ---- epilogue: out = x + relu(conv)
#pragma unroll
        for (int a = 0; a < TCO; ++a) {
            float* row = base + ((size_t)(co0+cofs+a) * S + s_cur) * L + l0 + lofs;
            if constexpr (TL == 4) {
                float4 xv = *(float4*)row;
                xv.x += fmaxf(acc[a][0], 0.0f);
                xv.y += fmaxf(acc[a][1], 0.0f);
                xv.z += fmaxf(acc[a][2], 0.0f);
                xv.w += fmaxf(acc[a][3], 0.0f);
                *(float4*)row = xv;
            } else {
                float2 xv = *(float2*)row;
                xv.x += fmaxf(acc[a][0], 0.0f);
                xv.y += fmaxf(acc[a][1], 0.0f);
                *(float2*)row = xv;
            }
        }

        __syncthreads();   // all stores in block issued; csm free
        if (i < S-1) {
            if (tid == 0) {
                red_rel_add1(ctr);
                const unsigned tgt = (unsigned)i * NB;
                while (ld_acq(ctr) < tgt) __nanosleep(64);
            }
            __syncthreads();
        }
    }
}

// ---------------------------------------------------------------------------
// Transpose [P, A, B] -> [P, B, A]
// ---------------------------------------------------------------------------
__global__ void transpose_kernel(const float* __restrict__ in,
                                 float* __restrict__ out, int A, int B)
{
    __shared__ float tile[32][33];
    const size_t p = blockIdx.z;
    const int b0 = blockIdx.x * 32;
    const int a0 = blockIdx.y * 32;
    const int tx = threadIdx.x, ty = threadIdx.y;
    const float* ip = in  + p * (size_t)A * B;
    float*       op = out + p * (size_t)A * B;
#pragma unroll
    for (int i = ty; i < 32; i += 8)
        tile[i][tx] = ip[(size_t)(a0+i)*B + (b0+tx)];
    __syncthreads();
#pragma unroll
    for (int i = ty; i < 32; i += 8)
        op[(size_t)(b0+i)*A + (a0+tx)] = tile[tx][i];
}

// Vertical: [B,C,S=H=128,L=W=256]; Horizontal (transposed): [B,C,S=W=256,L=H=128]
#define PASSV pass_kernel<32,64,2,4,128,256,256>
#define PASSH pass_kernel<32,32,2,2,256,128,256>

static constexpr int SMEM_V = (CCH*(64+8) + KS*(CCH*36+4)) * 4;  // 202896 B
static constexpr int SMEM_H = (CCH*(32+8) + KS*(CCH*36+4)) * 4;  // 186512 B

extern "C" void kernel_launch(void* const* d_in, const int* in_sizes, int n_in,
                              void* d_out, int out_size)
{
    const float* x    = (const float*)d_in[0];
    const float* w_ud = (const float*)d_in[1];
    const float* w_du = (const float*)d_in[2];
    const float* w_lr = (const float*)d_in[3];
    const float* w_rl = (const float*)d_in[4];
    float* buf = (float*)d_out;

    float* tbuf = nullptr;
    cudaGetSymbolAddress((void**)&tbuf, g_tmp);
    unsigned* ctr = nullptr;
    cudaGetSymbolAddress((void**)&ctr, g_ctr);

    cudaFuncSetAttribute(PASSV, cudaFuncAttributeMaxDynamicSharedMemorySize, SMEM_V);
    cudaFuncSetAttribute(PASSH, cudaFuncAttributeMaxDynamicSharedMemorySize, SMEM_H);

    // reset barrier counters (graph replays reuse the device globals)
    cudaMemsetAsync(ctr, 0, 4*sizeof(unsigned), 0);

    // buf <- x (passes run in-place)
    cudaMemcpyAsync(buf, x, (size_t)NTOT * sizeof(float),
                    cudaMemcpyDeviceToDevice, 0);

    dim3 gv(WW/64, CCH/32, BATCH);   // 4*4*8 = 128 blocks, 1/SM, all resident
    PASSV<<<gv, 256, SMEM_V>>>(buf, w_ud, ctr+0, 0);
    PASSV<<<gv, 256, SMEM_V>>>(buf, w_du, ctr+1, 1);

    transpose_kernel<<<dim3(WW/32, HH/32, BATCH*CCH), dim3(32,8)>>>(buf, tbuf, HH, WW);

    dim3 gh(HH/32, CCH/32, BATCH);   // 4*4*8 = 128 blocks
    PASSH<<<gh, 256, SMEM_H>>>(tbuf, w_lr, ctr+2, 0);
    PASSH<<<gh, 256, SMEM_H>>>(tbuf, w_rl, ctr+3, 1);

    transpose_kernel<<<dim3(HH/32, WW/32, BATCH*CCH), dim3(32,8)>>>(tbuf, buf, WW, HH);
}

// round 4
// speedup vs baseline: 3.6950x; 1.0232x over previous
#include <cuda_runtime.h>
#include <cstdint>

#define BATCH 8
#define CCH   128
#define HH    128
#define WW    256
#define KS    9
#define PADK  4
#define NTOT  (BATCH*CCH*HH*WW)

using ull = unsigned long long;

// Scratch buffer for transposed layout [B, C, W, H]
__device__ float g_tmp[NTOT];
// Grid-barrier counters, one per pass (reset each kernel_launch)
__device__ unsigned g_ctr[4];

__device__ __forceinline__ unsigned ld_acq(const unsigned* p) {
    unsigned v;
    asm volatile("ld.acquire.gpu.global.u32 %0, [%1];" : "=r"(v) : "l"(p) : "memory");
    return v;
}
__device__ __forceinline__ void red_rel_add1(unsigned* p) {
    asm volatile("red.release.gpu.global.add.u32 [%0], 1;" :: "l"(p) : "memory");
}

// Packed fp32 helpers (Blackwell f32x2 pipe: FFMA2 = 2 fp32 MACs per issue)
__device__ __forceinline__ ull pack2(float lo, float hi) {
    ull r; asm("mov.b64 %0, {%1, %2};" : "=l"(r) : "f"(lo), "f"(hi)); return r;
}
__device__ __forceinline__ void unpack2(ull v, float& lo, float& hi) {
    asm("mov.b64 {%0, %1}, %2;" : "=f"(lo), "=f"(hi) : "l"(v));
}
__device__ __forceinline__ ull fma2(ull a, ull b, ull c) {
    ull d; asm("fma.rn.f32x2 %0, %1, %2, %3;" : "=l"(d) : "l"(a), "l"(b), "l"(c));
    return d;
}

// ---------------------------------------------------------------------------
// Persistent pass kernel, FFMA2 packed over CO pairs.
// Layout [B, C, S, L]; scan S, conv along L. Each thread owns 2 adjacent co
// channels x TL adjacent l positions. Weight pair (w_co0,w_co1) is a direct
// LDS.64 (co-contiguous smem layout); carry operand is broadcast-packed.
// out[b,co,s,l] = buf[b,co,s,l] + relu( sum_{ci,k} w[co,ci,k]*prev[ci,l+k-4] )
// ---------------------------------------------------------------------------
template<int CO, int LT, int TL, int S, int L, int NT>
__global__ void __launch_bounds__(NT)
pass_kernel(float* __restrict__ buf, const float* __restrict__ wgt,
            unsigned* __restrict__ ctr, int reverse)
{
    constexpr int CLS = LT + 8;            // carry row stride (halo 4+4), even
    constexpr int CIS = CO;                // wsm ci stride (broadcast loads: no pad)
    constexpr int KST = CCH*CIS;           // wsm k stride
    static_assert(NT == (CO/2)*(LT/TL), "thread count mismatch");

    extern __shared__ float sm[];
    float* csm = sm;                       // [CCH][CLS]
    float* wsm = sm + CCH*CLS;             // [KS][CCH][CO]

    const int b   = blockIdx.z;
    const int co0 = blockIdx.y * CO;
    const int l0  = blockIdx.x * LT;
    const int tid = threadIdx.x;
    const unsigned NB = gridDim.x * gridDim.y * gridDim.z;

    float* base = buf + (size_t)b * CCH * S * L;

    // ---- weights once per pass: wgt[co][ci][k] -> wsm[k][ci][co] ----
    for (int idx = tid; idx < CO*CCH*KS; idx += NT) {
        int co = idx / (CCH*KS);
        int r  = idx % (CCH*KS);
        int ci = r / KS;
        int k  = r % KS;
        wsm[k*KST + ci*CIS + co] =
            wgt[(size_t)(co0+co)*CCH*KS + (size_t)ci*KS + k];
    }

    const int cog  = tid / (LT/TL);
    const int lg   = tid % (LT/TL);
    const int lofs = lg  * TL;
    const int cofs = cog * 2;

    for (int i = 1; i < S; ++i) {
        const int s_cur  = reverse ? (S-1-i) : i;
        const int s_prev = reverse ? (s_cur+1) : (s_cur-1);

        // ---- carry tile: previous finalized row, all ci, L-edge zero pad ----
        {
            const float* src = base + (size_t)s_prev * L;
#pragma unroll 4
            for (int idx = tid; idx < CCH*CLS; idx += NT) {
                int ci = idx / CLS;
                int j  = idx % CLS;
                int gl = l0 + j - PADK;
                float v = 0.0f;
                if (gl >= 0 && gl < L) v = src[(size_t)ci * S * L + gl];
                csm[idx] = v;
            }
        }
        __syncthreads();

        ull acc2[TL];
#pragma unroll
        for (int j = 0; j < TL; ++j) acc2[j] = 0ull;

#pragma unroll 2
        for (int ci = 0; ci < CCH; ++ci) {
            const float* crow = &csm[ci*CLS + lofs];
            float cf[TL+8];
            if constexpr ((TL & 3) == 0) {
#pragma unroll
                for (int j = 0; j < TL+8; j += 4) {
                    float4 v = *(const float4*)(crow + j);
                    cf[j]=v.x; cf[j+1]=v.y; cf[j+2]=v.z; cf[j+3]=v.w;
                }
            } else {
#pragma unroll
                for (int j = 0; j < TL+8; j += 2) {
                    float2 v = *(const float2*)(crow + j);
                    cf[j]=v.x; cf[j+1]=v.y;
                }
            }
            // broadcast-packed carry operands (c[m], c[m])
            ull cb[TL+8];
#pragma unroll
            for (int m = 0; m < TL+8; ++m) cb[m] = pack2(cf[m], cf[m]);

#pragma unroll
            for (int k = 0; k < KS; ++k) {
                // (w[co0], w[co1]) as one LDS.64 (2 distinct addrs/warp: bcast)
                ull wp = *(const ull*)&wsm[k*KST + ci*CIS + cofs];
#pragma unroll
                for (int j = 0; j < TL; ++j)
                    acc2[j] = fma2(wp, cb[j+k], acc2[j]);
            }
        }

        // ---- epilogue: out = x + relu(conv), two co rows ----
        float a0[TL], a1[TL];
#pragma unroll
        for (int j = 0; j < TL; ++j) unpack2(acc2[j], a0[j], a1[j]);

        {
            float* row0 = base + ((size_t)(co0+cofs)   * S + s_cur) * L + l0 + lofs;
            float* row1 = base + ((size_t)(co0+cofs+1) * S + s_cur) * L + l0 + lofs;
            if constexpr (TL == 4) {
                float4 x0 = *(float4*)row0;
                x0.x += fmaxf(a0[0],0.f); x0.y += fmaxf(a0[1],0.f);
                x0.z += fmaxf(a0[2],0.f); x0.w += fmaxf(a0[3],0.f);
                *(float4*)row0 = x0;
                float4 x1 = *(float4*)row1;
                x1.x += fmaxf(a1[0],0.f); x1.y += fmaxf(a1[1],0.f);
                x1.z += fmaxf(a1[2],0.f); x1.w += fmaxf(a1[3],0.f);
                *(float4*)row1 = x1;
            } else {
                float2 x0 = *(float2*)row0;
                x0.x += fmaxf(a0[0],0.f); x0.y += fmaxf(a0[1],0.f);
                *(float2*)row0 = x0;
                float2 x1 = *(float2*)row1;
                x1.x += fmaxf(a1[0],0.f); x1.y += fmaxf(a1[1],0.f);
                *(float2*)row1 = x1;
            }
        }

        __syncthreads();
        if (i < S-1) {
            if (tid == 0) {
                red_rel_add1(ctr);
                const unsigned tgt = (unsigned)i * NB;
                while (ld_acq(ctr) < tgt) __nanosleep(32);
            }
            __syncthreads();
        }
    }
}

// ---------------------------------------------------------------------------
// Transpose [P, A, B] -> [P, B, A]
// ---------------------------------------------------------------------------
__global__ void transpose_kernel(const float* __restrict__ in,
                                 float* __restrict__ out, int A, int B)
{
    __shared__ float tile[32][33];
    const size_t p = blockIdx.z;
    const int b0 = blockIdx.x * 32;
    const int a0 = blockIdx.y * 32;
    const int tx = threadIdx.x, ty = threadIdx.y;
    const float* ip = in  + p * (size_t)A * B;
    float*       op = out + p * (size_t)A * B;
#pragma unroll
    for (int i = ty; i < 32; i += 8)
        tile[i][tx] = ip[(size_t)(a0+i)*B + (b0+tx)];
    __syncthreads();
#pragma unroll
    for (int i = ty; i < 32; i += 8)
        op[(size_t)(b0+i)*A + (a0+tx)] = tile[tx][i];
}

// Vertical: [B,C,S=H=128,L=W=256]; Horizontal (transposed): [B,C,S=W=256,L=H=128]
#define PASSV pass_kernel<32,64,4,128,256,256>
#define PASSH pass_kernel<32,32,2,256,128,256>

static constexpr int SMEM_V = (CCH*(64+8) + KS*CCH*32) * 4;  // 184320 B
static constexpr int SMEM_H = (CCH*(32+8) + KS*CCH*32) * 4;  // 167936 B

extern "C" void kernel_launch(void* const* d_in, const int* in_sizes, int n_in,
                              void* d_out, int out_size)
{
    const float* x    = (const float*)d_in[0];
    const float* w_ud = (const float*)d_in[1];
    const float* w_du = (const float*)d_in[2];
    const float* w_lr = (const float*)d_in[3];
    const float* w_rl = (const float*)d_in[4];
    float* buf = (float*)d_out;

    float* tbuf = nullptr;
    cudaGetSymbolAddress((void**)&tbuf, g_tmp);
    unsigned* ctr = nullptr;
    cudaGetSymbolAddress((void**)&ctr, g_ctr);

    cudaFuncSetAttribute(PASSV, cudaFuncAttributeMaxDynamicSharedMemorySize, SMEM_V);
    cudaFuncSetAttribute(PASSH, cudaFuncAttributeMaxDynamicSharedMemorySize, SMEM_H);

    // reset barrier counters (each graph replay re-runs this)
    cudaMemsetAsync(ctr, 0, 4*sizeof(unsigned), 0);

    // buf <- x (passes run in-place)
    cudaMemcpyAsync(buf, x, (size_t)NTOT * sizeof(float),
                    cudaMemcpyDeviceToDevice, 0);

    dim3 gv(WW/64, CCH/32, BATCH);   // 128 blocks, 1/SM, all resident
    PASSV<<<gv, 256, SMEM_V>>>(buf, w_ud, ctr+0, 0);
    PASSV<<<gv, 256, SMEM_V>>>(buf, w_du, ctr+1, 1);

    transpose_kernel<<<dim3(WW/32, HH/32, BATCH*CCH), dim3(32,8)>>>(buf, tbuf, HH, WW);

    dim3 gh(HH/32, CCH/32, BATCH);   // 128 blocks
    PASSH<<<gh, 256, SMEM_H>>>(tbuf, w_lr, ctr+2, 0);
    PASSH<<<gh, 256, SMEM_H>>>(tbuf, w_rl, ctr+3, 1);

    transpose_kernel<<<dim3(HH/32, WW/32, BATCH*CCH), dim3(32,8)>>>(tbuf, buf, WW, HH);
}

// round 6
// speedup vs baseline: 5.3726x; 1.4540x over previous
#include <cuda_runtime.h>
#include <cuda_bf16.h>
#include <cstdint>

#define BATCH 8
#define CCH   128
#define HH    128
#define WW    256
#define KS    9
#define NTOT  (BATCH*CCH*HH*WW)

__device__ float    g_tmp[NTOT];   // transposed layout scratch
__device__ unsigned g_ctr[4];      // grid-barrier counters

__device__ __forceinline__ unsigned ld_acq(const unsigned* p) {
    unsigned v;
    asm volatile("ld.acquire.gpu.global.u32 %0, [%1];" : "=r"(v) : "l"(p) : "memory");
    return v;
}
__device__ __forceinline__ void red_rel_add1(unsigned* p) {
    asm volatile("red.release.gpu.global.add.u32 [%0], 1;" :: "l"(p) : "memory");
}
__device__ __forceinline__ uint32_t smem_u32(const void* p) {
    uint32_t a;
    asm("{ .reg .u64 t; cvta.to.shared.u64 t, %1; cvt.u32.u64 %0, t; }"
        : "=r"(a) : "l"(p));
    return a;
}
__device__ __forceinline__ void ldsm4(uint32_t addr, uint32_t& r0, uint32_t& r1,
                                      uint32_t& r2, uint32_t& r3) {
    asm volatile("ldmatrix.sync.aligned.m8n8.x4.shared.b16 {%0,%1,%2,%3}, [%4];"
                 : "=r"(r0), "=r"(r1), "=r"(r2), "=r"(r3) : "r"(addr));
}
__device__ __forceinline__ void mma_bf16(float* c, const uint32_t* a,
                                         uint32_t b0, uint32_t b1) {
    asm volatile(
        "mma.sync.aligned.m16n8k16.row.col.f32.bf16.bf16.f32 "
        "{%0,%1,%2,%3}, {%4,%5,%6,%7}, {%8,%9}, {%0,%1,%2,%3};"
        : "+f"(c[0]), "+f"(c[1]), "+f"(c[2]), "+f"(c[3])
        : "r"(a[0]), "r"(a[1]), "r"(a[2]), "r"(a[3]), "r"(b0), "r"(b1));
}

// ---------------------------------------------------------------------------
// Persistent HMMA pass kernel. Layout [B, C, S, L]; scan S, conv along L.
// Block = (l-tile M, co-slice 32, batch). K-units = 3 split-terms x 9 taps x
// 8 ci-chunks = 216, round-robined over 8 warps (27 each); each warp carries
// full M x 32 accumulators; partials combined via 2-round smem reduction.
// A (carry, bf16 hi/lo, [row=l'][ci], stride 136) rebuilt per step; tap shift
// = +tap row offset. B (weights, bf16 hi/lo, [tap][co][ci]) resident per pass.
// out[l,co] = x + relu( sum_{ci,k} w[co,ci,k]*prev[ci,l+k-4] )
// ---------------------------------------------------------------------------
template<int S, int L, int M>
__global__ void __launch_bounds__(256, 1)
pass_kernel(float* __restrict__ buf, const float* __restrict__ wgt,
            unsigned* __restrict__ ctr, int reverse)
{
    constexpr int ROWS = M + 8;
    constexpr int AST  = 136;                 // A row stride (bf16 elems), 272B
    constexpr int NST  = 136;                 // B row stride
    constexpr int MT   = M / 16;              // m16 tiles per block
    constexpr int A_SZ = ROWS * AST * 2;      // bytes per A split
    constexpr int B_SZ = KS * 32 * NST * 2;   // bytes per B split
    constexpr int GPB  = 256 / M;             // epilogue co-groups
    constexpr int CPT  = 32 / GPB;            // co per thread in epilogue

    extern __shared__ char sm[];
    __nv_bfloat16* A_p[2] = { (__nv_bfloat16*)sm, (__nv_bfloat16*)(sm + A_SZ) };
    __nv_bfloat16* B_p[2] = { (__nv_bfloat16*)(sm + 2*A_SZ),
                              (__nv_bfloat16*)(sm + 2*A_SZ + B_SZ) };
    float* stage = (float*)sm;                // aliases A (temporal separation)
    const uint32_t smb = smem_u32(sm);
    const uint32_t smA[2] = { smb, smb + (uint32_t)A_SZ };
    const uint32_t smB[2] = { smb + 2u*A_SZ, smb + 2u*A_SZ + (uint32_t)B_SZ };

    const int tid  = threadIdx.x;
    const int wid  = tid >> 5;
    const int lane = tid & 31;
    const int b    = blockIdx.z;
    const int co0  = blockIdx.y * 32;
    const int l0   = blockIdx.x * M;
    const unsigned NB = gridDim.x * gridDim.y * gridDim.z;

    float* base = buf + (size_t)b * CCH * S * L;

    // ---- resident weights: wgt[co][ci][k] -> Bt[k][co][ci] hi/lo ----
    for (int idx = tid; idx < 32 * CCH * KS; idx += 256) {
        int co = idx / (CCH * KS);
        int r  = idx % (CCH * KS);
        int ci = r / KS;
        int k  = r % KS;
        float v = wgt[(size_t)(co0 + co) * CCH * KS + (size_t)ci * KS + k];
        __nv_bfloat16 hi = __float2bfloat16(v);
        __nv_bfloat16 lo = __float2bfloat16(v - __bfloat162float(hi));
        int off = (k * 32 + co) * NST + ci;
        B_p[0][off] = hi;
        B_p[1][off] = lo;
    }
    __syncthreads();

    // ldmatrix per-lane offsets (tiles: (r0,k0),(r8,k0),(r0,k8),(r8,k8))
    const int lt   = lane >> 3;
    const int lrow = (lane & 7) + ((lt & 1) << 3);
    const int lk   = (lt >> 1) << 3;

    for (int i = 1; i < S; ++i) {
        const int s_cur  = reverse ? (S - 1 - i) : i;
        const int s_prev = reverse ? (s_cur + 1) : (s_cur - 1);

        // ---- A build: carry row -> bf16 hi/lo [l'][ci] ----
        {
            const float* src = base + (size_t)s_prev * L;
            for (int idx = tid; idx < CCH * ROWS; idx += 256) {
                int ci = idx / ROWS;
                int r  = idx % ROWS;
                int gl = l0 - 4 + r;
                float v = (gl >= 0 && gl < L) ? src[(size_t)ci * S * L + gl] : 0.0f;
                __nv_bfloat16 hi = __float2bfloat16(v);
                __nv_bfloat16 lo = __float2bfloat16(v - __bfloat162float(hi));
                A_p[0][r * AST + ci] = hi;
                A_p[1][r * AST + ci] = lo;
            }
        }
        __syncthreads();

        // ---- HMMA: 27 (term,tap,kc) units per warp, full M x 32 accs ----
        float acc[MT][4][4];
#pragma unroll
        for (int mt = 0; mt < MT; ++mt)
#pragma unroll
            for (int nt = 0; nt < 4; ++nt)
#pragma unroll
                for (int e = 0; e < 4; ++e) acc[mt][nt][e] = 0.0f;

        for (int u = wid; u < 216; u += 8) {
            const int term = u / 72;
            const int rem  = u % 72;
            const int tap  = rem >> 3;
            const int kc   = rem & 7;
            const uint32_t aB = smA[term == 1];
            const uint32_t bB = smB[term == 2];

            uint32_t bb[2][4];
#pragma unroll
            for (int nt = 0; nt < 2; ++nt) {
                uint32_t addr = bB +
                    (uint32_t)(((tap * 32 + nt * 16 + lrow) * NST + kc * 16 + lk) * 2);
                ldsm4(addr, bb[nt][0], bb[nt][1], bb[nt][2], bb[nt][3]);
            }
#pragma unroll
            for (int mt = 0; mt < MT; ++mt) {
                uint32_t a[4];
                uint32_t addr = aB +
                    (uint32_t)(((mt * 16 + tap + lrow) * AST + kc * 16 + lk) * 2);
                ldsm4(addr, a[0], a[1], a[2], a[3]);
                mma_bf16(acc[mt][0], a, bb[0][0], bb[0][2]);
                mma_bf16(acc[mt][1], a, bb[0][1], bb[0][3]);
                mma_bf16(acc[mt][2], a, bb[1][0], bb[1][2]);
                mma_bf16(acc[mt][3], a, bb[1][1], bb[1][3]);
            }
        }
        __syncthreads();   // all ldmatrix reads of A done; stage may alias A

        // ---- reduce 8 partials -> 4 regions -> epilogue sum ----
        const int region = wid & 3;
        const int row0   = lane >> 2;
        const int colb   = (lane & 3) * 2;
        if (wid < 4) {
#pragma unroll
            for (int mt = 0; mt < MT; ++mt)
#pragma unroll
                for (int nt = 0; nt < 4; ++nt) {
                    float* p = stage + (size_t)(region * M + mt * 16 + row0) * 33
                                     + nt * 8 + colb;
                    p[0] = acc[mt][nt][0];  p[1] = acc[mt][nt][1];
                    p[8*33] = acc[mt][nt][2];  p[8*33 + 1] = acc[mt][nt][3];
                }
        }
        __syncthreads();
        if (wid >= 4) {
#pragma unroll
            for (int mt = 0; mt < MT; ++mt)
#pragma unroll
                for (int nt = 0; nt < 4; ++nt) {
                    float* p = stage + (size_t)(region * M + mt * 16 + row0) * 33
                                     + nt * 8 + colb;
                    p[0] += acc[mt][nt][0];  p[1] += acc[mt][nt][1];
                    p[8*33] += acc[mt][nt][2];  p[8*33 + 1] += acc[mt][nt][3];
                }
        }
        __syncthreads();

        // ---- epilogue: out = x + relu( sum of 4 regions ) ----
        {
            const int m = tid % M;
            const int g = tid / M;
#pragma unroll
            for (int c = 0; c < CPT; ++c) {
                const int co = g * CPT + c;
                float v = stage[(size_t)m * 33 + co]
                        + stage[(size_t)(M + m) * 33 + co]
                        + stage[(size_t)(2 * M + m) * 33 + co]
                        + stage[(size_t)(3 * M + m) * 33 + co];
                float* p = base + ((size_t)(co0 + co) * S + s_cur) * L + l0 + m;
                *p = *p + fmaxf(v, 0.0f);
            }
        }

        __threadfence();
        __syncthreads();
        if (i < S - 1) {
            if (tid == 0) {
                red_rel_add1(ctr);
                const unsigned tgt = (unsigned)i * NB;
                while (ld_acq(ctr) < tgt) __nanosleep(32);
            }
            __syncthreads();
        }
    }
}

// ---------------------------------------------------------------------------
// Transpose [P, A, B] -> [P, B, A]
// ---------------------------------------------------------------------------
__global__ void transpose_kernel(const float* __restrict__ in,
                                 float* __restrict__ out, int A, int B)
{
    __shared__ float tile[32][33];
    const size_t p = blockIdx.z;
    const int b0 = blockIdx.x * 32;
    const int a0 = blockIdx.y * 32;
    const int tx = threadIdx.x, ty = threadIdx.y;
    const float* ip = in  + p * (size_t)A * B;
    float*       op = out + p * (size_t)A * B;
#pragma unroll
    for (int i = ty; i < 32; i += 8)
        tile[i][tx] = ip[(size_t)(a0+i)*B + (b0+tx)];
    __syncthreads();
#pragma unroll
    for (int i = ty; i < 32; i += 8)
        op[(size_t)(b0+i)*A + (a0+tx)] = tile[tx][i];
}

// Vertical: [B,C,S=H=128,L=W=256], M=64. Horizontal (transposed): S=256,L=128, M=32.
#define PASSV pass_kernel<128,256,64>
#define PASSH pass_kernel<256,128,32>

static constexpr int SMEM_V = 2*(72*136*2) + 2*(KS*32*136*2);  // 39168+156672=195840
static constexpr int SMEM_H = 2*(40*136*2) + 2*(KS*32*136*2);  // 21760+156672=178432

extern "C" void kernel_launch(void* const* d_in, const int* in_sizes, int n_in,
                              void* d_out, int out_size)
{
    const float* x    = (const float*)d_in[0];
    const float* w_ud = (const float*)d_in[1];
    const float* w_du = (const float*)d_in[2];
    const float* w_lr = (const float*)d_in[3];
    const float* w_rl = (const float*)d_in[4];
    float* buf = (float*)d_out;

    float* tbuf = nullptr;
    cudaGetSymbolAddress((void**)&tbuf, g_tmp);
    unsigned* ctr = nullptr;
    cudaGetSymbolAddress((void**)&ctr, g_ctr);

    cudaFuncSetAttribute(PASSV, cudaFuncAttributeMaxDynamicSharedMemorySize, SMEM_V);
    cudaFuncSetAttribute(PASSH, cudaFuncAttributeMaxDynamicSharedMemorySize, SMEM_H);

    cudaMemsetAsync(ctr, 0, 4*sizeof(unsigned), 0);
    cudaMemcpyAsync(buf, x, (size_t)NTOT * sizeof(float),
                    cudaMemcpyDeviceToDevice, 0);

    dim3 gv(WW/64, 4, BATCH);    // 4*4*8 = 128 blocks, 1/SM, all resident
    PASSV<<<gv, 256, SMEM_V>>>(buf, w_ud, ctr+0, 0);
    PASSV<<<gv, 256, SMEM_V>>>(buf, w_du, ctr+1, 1);

    transpose_kernel<<<dim3(WW/32, HH/32, BATCH*CCH), dim3(32,8)>>>(buf, tbuf, HH, WW);

    dim3 gh(HH/32, 4, BATCH);    // 4*4*8 = 128 blocks
    PASSH<<<gh, 256, SMEM_H>>>(tbuf, w_lr, ctr+2, 0);
    PASSH<<<gh, 256, SMEM_H>>>(tbuf, w_rl, ctr+3, 1);

    transpose_kernel<<<dim3(HH/32, WW/32, BATCH*CCH), dim3(32,8)>>>(tbuf, buf, WW, HH);
}

// round 7
// speedup vs baseline: 5.7333x; 1.0671x over previous
#include <cuda_runtime.h>
#include <cuda_bf16.h>
#include <cstdint>

#define BATCH 8
#define CCH   128
#define HH    128
#define WW    256
#define KS    9
#define NTOT  (BATCH*CCH*HH*WW)

__device__ float    g_tmp[NTOT];        // transposed layout scratch
// per-(pass,batch) barrier counters, 256B apart (distinct LTS slices)
__device__ unsigned g_ctrs[4][BATCH][64];

__device__ __forceinline__ unsigned ld_acq(const unsigned* p) {
    unsigned v;
    asm volatile("ld.acquire.gpu.global.u32 %0, [%1];" : "=r"(v) : "l"(p) : "memory");
    return v;
}
__device__ __forceinline__ void red_rel_add1(unsigned* p) {
    asm volatile("red.release.gpu.global.add.u32 [%0], 1;" :: "l"(p) : "memory");
}
__device__ __forceinline__ uint32_t smem_u32(const void* p) {
    uint32_t a;
    asm("{ .reg .u64 t; cvta.to.shared.u64 t, %1; cvt.u32.u64 %0, t; }"
        : "=r"(a) : "l"(p));
    return a;
}
__device__ __forceinline__ void ldsm4(uint32_t addr, uint32_t& r0, uint32_t& r1,
                                      uint32_t& r2, uint32_t& r3) {
    asm volatile("ldmatrix.sync.aligned.m8n8.x4.shared.b16 {%0,%1,%2,%3}, [%4];"
                 : "=r"(r0), "=r"(r1), "=r"(r2), "=r"(r3) : "r"(addr));
}
__device__ __forceinline__ void mma_bf16(float* c, const uint32_t* a,
                                         uint32_t b0, uint32_t b1) {
    asm volatile(
        "mma.sync.aligned.m16n8k16.row.col.f32.bf16.bf16.f32 "
        "{%0,%1,%2,%3}, {%4,%5,%6,%7}, {%8,%9}, {%0,%1,%2,%3};"
        : "+f"(c[0]), "+f"(c[1]), "+f"(c[2]), "+f"(c[3])
        : "r"(a[0]), "r"(a[1]), "r"(a[2]), "r"(a[3]), "r"(b0), "r"(b1));
}

// ---------------------------------------------------------------------------
// Persistent HMMA pass kernel. Layout [B, C, S, L]; scan S, conv along L.
// Block = (l-tile M, co-slice 32, batch). K-units = 3 split-terms x 9 taps x
// 8 ci-chunks = 216, round-robined over 8 warps; full M x 32 accumulators per
// warp; partials combined via 2-round smem reduction. Steps separated by a
// PER-BATCH 16-block release/acquire barrier (blocks of different batches
// never share data -> independent counters, batches drift independently).
// out[l,co] = x + relu( sum_{ci,k} w[co,ci,k]*prev[ci,l+k-4] )
// ---------------------------------------------------------------------------
template<int S, int L, int M>
__global__ void __launch_bounds__(256, 1)
pass_kernel(float* __restrict__ buf, const float* __restrict__ wgt,
            unsigned* __restrict__ ctr_base, int reverse)
{
    constexpr int ROWS = M + 8;
    constexpr int AST  = 136;                 // A row stride (bf16 elems)
    constexpr int NST  = 136;                 // B row stride
    constexpr int MT   = M / 16;              // m16 tiles per block
    constexpr int A_SZ = ROWS * AST * 2;      // bytes per A split
    constexpr int B_SZ = KS * 32 * NST * 2;   // bytes per B split
    constexpr int GPB  = 256 / M;             // epilogue co-groups
    constexpr int CPT  = 32 / GPB;            // co per thread in epilogue

    extern __shared__ char sm[];
    __nv_bfloat16* A_p[2] = { (__nv_bfloat16*)sm, (__nv_bfloat16*)(sm + A_SZ) };
    __nv_bfloat16* B_p[2] = { (__nv_bfloat16*)(sm + 2*A_SZ),
                              (__nv_bfloat16*)(sm + 2*A_SZ + B_SZ) };
    float* stage = (float*)sm;                // aliases A (temporal separation)
    const uint32_t smb = smem_u32(sm);
    const uint32_t smA[2] = { smb, smb + (uint32_t)A_SZ };
    const uint32_t smB[2] = { smb + 2u*A_SZ, smb + 2u*A_SZ + (uint32_t)B_SZ };

    const int tid  = threadIdx.x;
    const int wid  = tid >> 5;
    const int lane = tid & 31;
    const int b    = blockIdx.z;
    const int co0  = blockIdx.y * 32;
    const int l0   = blockIdx.x * M;
    const unsigned NB = gridDim.x * gridDim.y;          // blocks per batch
    unsigned* ctr = ctr_base + (size_t)b * 64;          // this batch's counter

    float* base = buf + (size_t)b * CCH * S * L;

    // ---- resident weights: wgt[co][ci][k] -> Bt[k][co][ci] hi/lo ----
    for (int idx = tid; idx < 32 * CCH * KS; idx += 256) {
        int co = idx / (CCH * KS);
        int r  = idx % (CCH * KS);
        int ci = r / KS;
        int k  = r % KS;
        float v = wgt[(size_t)(co0 + co) * CCH * KS + (size_t)ci * KS + k];
        __nv_bfloat16 hi = __float2bfloat16(v);
        __nv_bfloat16 lo = __float2bfloat16(v - __bfloat162float(hi));
        int off = (k * 32 + co) * NST + ci;
        B_p[0][off] = hi;
        B_p[1][off] = lo;
    }
    __syncthreads();

    // ldmatrix per-lane offsets (tiles: (r0,k0),(r8,k0),(r0,k8),(r8,k8))
    const int lt   = lane >> 3;
    const int lrow = (lane & 7) + ((lt & 1) << 3);
    const int lk   = (lt >> 1) << 3;

    for (int i = 1; i < S; ++i) {
        const int s_cur  = reverse ? (S - 1 - i) : i;
        const int s_prev = reverse ? (s_cur + 1) : (s_cur - 1);

        // ---- A build: carry row -> bf16 hi/lo [l'][ci] (unrolled for MLP) ----
        {
            const float* src = base + (size_t)s_prev * L;
#pragma unroll 6
            for (int idx = tid; idx < CCH * ROWS; idx += 256) {
                int ci = idx / ROWS;
                int r  = idx % ROWS;
                int gl = l0 - 4 + r;
                float v = (gl >= 0 && gl < L) ? src[(size_t)ci * S * L + gl] : 0.0f;
                __nv_bfloat16 hi = __float2bfloat16(v);
                __nv_bfloat16 lo = __float2bfloat16(v - __bfloat162float(hi));
                A_p[0][r * AST + ci] = hi;
                A_p[1][r * AST + ci] = lo;
            }
        }
        __syncthreads();

        // ---- HMMA: 27 (term,tap,kc) units per warp, full M x 32 accs ----
        float acc[MT][4][4];
#pragma unroll
        for (int mt = 0; mt < MT; ++mt)
#pragma unroll
            for (int nt = 0; nt < 4; ++nt)
#pragma unroll
                for (int e = 0; e < 4; ++e) acc[mt][nt][e] = 0.0f;

        for (int u = wid; u < 216; u += 8) {
            const int term = u / 72;
            const int rem  = u % 72;
            const int tap  = rem >> 3;
            const int kc   = rem & 7;
            const uint32_t aB = smA[term == 1];
            const uint32_t bB = smB[term == 2];

            uint32_t bb[2][4];
#pragma unroll
            for (int nt = 0; nt < 2; ++nt) {
                uint32_t addr = bB +
                    (uint32_t)(((tap * 32 + nt * 16 + lrow) * NST + kc * 16 + lk) * 2);
                ldsm4(addr, bb[nt][0], bb[nt][1], bb[nt][2], bb[nt][3]);
            }
#pragma unroll
            for (int mt = 0; mt < MT; ++mt) {
                uint32_t a[4];
                uint32_t addr = aB +
                    (uint32_t)(((mt * 16 + tap + lrow) * AST + kc * 16 + lk) * 2);
                ldsm4(addr, a[0], a[1], a[2], a[3]);
                mma_bf16(acc[mt][0], a, bb[0][0], bb[0][2]);
                mma_bf16(acc[mt][1], a, bb[0][1], bb[0][3]);
                mma_bf16(acc[mt][2], a, bb[1][0], bb[1][2]);
                mma_bf16(acc[mt][3], a, bb[1][1], bb[1][3]);
            }
        }
        __syncthreads();   // all ldmatrix reads of A done; stage may alias A

        // ---- reduce 8 partials -> 4 regions -> epilogue sum ----
        const int region = wid & 3;
        const int row0   = lane >> 2;
        const int colb   = (lane & 3) * 2;
        if (wid < 4) {
#pragma unroll
            for (int mt = 0; mt < MT; ++mt)
#pragma unroll
                for (int nt = 0; nt < 4; ++nt) {
                    float* p = stage + (size_t)(region * M + mt * 16 + row0) * 33
                                     + nt * 8 + colb;
                    p[0] = acc[mt][nt][0];  p[1] = acc[mt][nt][1];
                    p[8*33] = acc[mt][nt][2];  p[8*33 + 1] = acc[mt][nt][3];
                }
        }
        __syncthreads();
        if (wid >= 4) {
#pragma unroll
            for (int mt = 0; mt < MT; ++mt)
#pragma unroll
                for (int nt = 0; nt < 4; ++nt) {
                    float* p = stage + (size_t)(region * M + mt * 16 + row0) * 33
                                     + nt * 8 + colb;
                    p[0] += acc[mt][nt][0];  p[1] += acc[mt][nt][1];
                    p[8*33] += acc[mt][nt][2];  p[8*33 + 1] += acc[mt][nt][3];
                }
        }
        __syncthreads();

        // ---- epilogue: out = x + relu( sum of 4 regions ) ----
        {
            const int m = tid % M;
            const int g = tid / M;
#pragma unroll
            for (int c = 0; c < CPT; ++c) {
                const int co = g * CPT + c;
                float v = stage[(size_t)m * 33 + co]
                        + stage[(size_t)(M + m) * 33 + co]
                        + stage[(size_t)(2 * M + m) * 33 + co]
                        + stage[(size_t)(3 * M + m) * 33 + co];
                float* p = base + ((size_t)(co0 + co) * S + s_cur) * L + l0 + m;
                *p = *p + fmaxf(v, 0.0f);
            }
        }

        // ---- per-batch grid barrier (release/acquire; 16 blocks) ----
        __syncthreads();            // all epilogue stores issued block-wide
        if (i < S - 1) {
            if (tid == 0) {
                red_rel_add1(ctr);
                const unsigned tgt = (unsigned)i * NB;
                while (ld_acq(ctr) < tgt) __nanosleep(16);
            }
            __syncthreads();
        }
    }
}

// ---------------------------------------------------------------------------
// Transpose [P, A, B] -> [P, B, A]
// ---------------------------------------------------------------------------
__global__ void transpose_kernel(const float* __restrict__ in,
                                 float* __restrict__ out, int A, int B)
{
    __shared__ float tile[32][33];
    const size_t p = blockIdx.z;
    const int b0 = blockIdx.x * 32;
    const int a0 = blockIdx.y * 32;
    const int tx = threadIdx.x, ty = threadIdx.y;
    const float* ip = in  + p * (size_t)A * B;
    float*       op = out + p * (size_t)A * B;
#pragma unroll
    for (int i = ty; i < 32; i += 8)
        tile[i][tx] = ip[(size_t)(a0+i)*B + (b0+tx)];
    __syncthreads();
#pragma unroll
    for (int i = ty; i < 32; i += 8)
        op[(size_t)(b0+i)*A + (a0+tx)] = tile[tx][i];
}

// Vertical: [B,C,S=H=128,L=W=256], M=64. Horizontal (transposed): S=256,L=128, M=32.
#define PASSV pass_kernel<128,256,64>
#define PASSH pass_kernel<256,128,32>

static constexpr int SMEM_V = 2*(72*136*2) + 2*(KS*32*136*2);  // 195840
static constexpr int SMEM_H = 2*(40*136*2) + 2*(KS*32*136*2);  // 178432

extern "C" void kernel_launch(void* const* d_in, const int* in_sizes, int n_in,
                              void* d_out, int out_size)
{
    const float* x    = (const float*)d_in[0];
    const float* w_ud = (const float*)d_in[1];
    const float* w_du = (const float*)d_in[2];
    const float* w_lr = (const float*)d_in[3];
    const float* w_rl = (const float*)d_in[4];
    float* buf = (float*)d_out;

    float* tbuf = nullptr;
    cudaGetSymbolAddress((void**)&tbuf, g_tmp);
    unsigned* ctr = nullptr;
    cudaGetSymbolAddress((void**)&ctr, g_ctrs);

    cudaFuncSetAttribute(PASSV, cudaFuncAttributeMaxDynamicSharedMemorySize, SMEM_V);
    cudaFuncSetAttribute(PASSH, cudaFuncAttributeMaxDynamicSharedMemorySize, SMEM_H);

    cudaMemsetAsync(ctr, 0, 4*BATCH*64*sizeof(unsigned), 0);
    cudaMemcpyAsync(buf, x, (size_t)NTOT * sizeof(float),
                    cudaMemcpyDeviceToDevice, 0);

    const unsigned PSTRIDE = BATCH * 64;   // counters per pass

    dim3 gv(WW/64, 4, BATCH);    // 16 blocks/batch, 128 total, 1/SM
    PASSV<<<gv, 256, SMEM_V>>>(buf, w_ud, ctr + 0*PSTRIDE, 0);
    PASSV<<<gv, 256, SMEM_V>>>(buf, w_du, ctr + 1*PSTRIDE, 1);

    transpose_kernel<<<dim3(WW/32, HH/32, BATCH*CCH), dim3(32,8)>>>(buf, tbuf, HH, WW);

    dim3 gh(HH/32, 4, BATCH);    // 16 blocks/batch, 128 total
    PASSH<<<gh, 256, SMEM_H>>>(tbuf, w_lr, ctr + 2*PSTRIDE, 0);
    PASSH<<<gh, 256, SMEM_H>>>(tbuf, w_rl, ctr + 3*PSTRIDE, 1);

    transpose_kernel<<<dim3(HH/32, WW/32, BATCH*CCH), dim3(32,8)>>>(tbuf, buf, WW, HH);
}

// round 8
// speedup vs baseline: 6.5058x; 1.1347x over previous
#include <cuda_runtime.h>
#include <cuda_fp16.h>
#include <cstdint>

#define BATCH 8
#define CCH   128
#define HH    128
#define WW    256
#define KS    9
#define NTOT  (BATCH*CCH*HH*WW)

__device__ float    g_tmp[NTOT];        // transposed layout scratch
// per-(pass,batch) barrier counters, 256B apart (distinct LTS slices)
__device__ unsigned g_ctrs[4][BATCH][64];

__device__ __forceinline__ unsigned ld_acq(const unsigned* p) {
    unsigned v;
    asm volatile("ld.acquire.gpu.global.u32 %0, [%1];" : "=r"(v) : "l"(p) : "memory");
    return v;
}
__device__ __forceinline__ void red_rel_add1(unsigned* p) {
    asm volatile("red.release.gpu.global.add.u32 [%0], 1;" :: "l"(p) : "memory");
}
__device__ __forceinline__ uint32_t smem_u32(const void* p) {
    uint32_t a;
    asm("{ .reg .u64 t; cvta.to.shared.u64 t, %1; cvt.u32.u64 %0, t; }"
        : "=r"(a) : "l"(p));
    return a;
}
__device__ __forceinline__ void ldsm4(uint32_t addr, uint32_t& r0, uint32_t& r1,
                                      uint32_t& r2, uint32_t& r3) {
    asm volatile("ldmatrix.sync.aligned.m8n8.x4.shared.b16 {%0,%1,%2,%3}, [%4];"
                 : "=r"(r0), "=r"(r1), "=r"(r2), "=r"(r3) : "r"(addr));
}
__device__ __forceinline__ void ldsm2(uint32_t addr, uint32_t& r0, uint32_t& r1) {
    asm volatile("ldmatrix.sync.aligned.m8n8.x2.shared.b16 {%0,%1}, [%2];"
                 : "=r"(r0), "=r"(r1) : "r"(addr));
}
__device__ __forceinline__ void mma_f16(float* c, const uint32_t* a,
                                        uint32_t b0, uint32_t b1) {
    asm volatile(
        "mma.sync.aligned.m16n8k16.row.col.f32.f16.f16.f32 "
        "{%0,%1,%2,%3}, {%4,%5,%6,%7}, {%8,%9}, {%0,%1,%2,%3};"
        : "+f"(c[0]), "+f"(c[1]), "+f"(c[2]), "+f"(c[3])
        : "r"(a[0]), "r"(a[1]), "r"(a[2]), "r"(a[3]), "r"(b0), "r"(b1));
}

// ---------------------------------------------------------------------------
// Persistent HMMA pass kernel, fp16, 2-term split on A (carry) only.
// Layout [B, C, S, L]; scan S, conv along L. Block = (l-tile M=64, co-slice
// CO, batch). Occupancy 2 (co-resident blocks hide sync/L2 latency).
// Warp w owns k16-chunk kc=w; iterates term(2) x tap(9) at compile time.
// Each warp holds full 64 x CO accumulators; 8 partials summed via stage.
// out[l,co] = x + relu( sum_{ci,k} w[co,ci,k]*prev[ci,l+k-4] )
// ---------------------------------------------------------------------------
template<int S, int L, int CO>
__global__ void __launch_bounds__(256, 2)
pass_kernel(float* __restrict__ buf, const float* __restrict__ wgt,
            unsigned* __restrict__ ctr_base, int reverse)
{
    constexpr int M    = 64;
    constexpr int ROWS = M + 8;               // 72 (halo 4+4)
    constexpr int AST  = 136;                 // fp16 row stride
    constexpr int MT   = M / 16;              // 4
    constexpr int NT   = CO / 8;              // 2 (V) or 1 (H)
    constexpr int A_SZ = ROWS * AST * 2;      // 19584 B per split
    constexpr int B_SZ = KS * CO * AST * 2;   // weights
    constexpr int SST  = CO + 1;              // stage row stride (floats)

    extern __shared__ char sm[];
    __half* A_p[2] = { (__half*)sm, (__half*)(sm + A_SZ) };
    __half* B_w    = (__half*)(sm + 2*A_SZ);
    float*  stage  = (float*)(sm + 2*A_SZ + B_SZ);   // 8 regions x M x SST
    const uint32_t smb = smem_u32(sm);
    const uint32_t smA[2] = { smb, smb + (uint32_t)A_SZ };
    const uint32_t smB    = smb + 2u*A_SZ;

    const int tid  = threadIdx.x;
    const int wid  = tid >> 5;
    const int lane = tid & 31;
    const int b    = blockIdx.z;
    const int co0  = blockIdx.y * CO;
    const int l0   = blockIdx.x * M;
    const unsigned NB = gridDim.x * gridDim.y;       // blocks per batch
    unsigned* ctr = ctr_base + (size_t)b * 64;

    float* base = buf + (size_t)b * CCH * S * L;

    // ---- resident weights (single fp16): wgt[co][ci][k] -> B[tap][co][ci] ----
    for (int idx = tid; idx < CO * CCH * KS; idx += 256) {
        int co = idx / (CCH * KS);
        int r  = idx % (CCH * KS);
        int ci = r / KS;
        int k  = r % KS;
        float v = wgt[(size_t)(co0 + co) * CCH * KS + (size_t)ci * KS + k];
        B_w[(k * CO + co) * AST + ci] = __float2half_rn(v);
    }
    __syncthreads();

    // ldmatrix lane mapping (x4 tiles: (r0,k0),(r8,k0),(r0,k8),(r8,k8))
    const int lt   = lane >> 3;
    const int lrow = (lane & 7) + ((lt & 1) << 3);
    const int lk   = (lt >> 1) << 3;
    // x2 mapping for CO=8 B tiles: lanes 0-7 (co,k0), 8-15 (co,k8)
    const int l2row = lane & 7;
    const int l2k   = ((lane >> 3) & 1) << 3;

    const int kcb = wid * 16;     // this warp's k16-chunk (ci offset)

    for (int i = 1; i < S; ++i) {
        const int s_cur  = reverse ? (S - 1 - i) : i;
        const int s_prev = reverse ? (s_cur + 1) : (s_cur - 1);

        // ---- A build: carry row -> fp16 hi/lo [l'][ci] ----
        {
            const float* src = base + (size_t)s_prev * L;
#pragma unroll 6
            for (int idx = tid; idx < CCH * ROWS; idx += 256) {
                int ci = idx / ROWS;
                int r  = idx % ROWS;
                int gl = l0 - 4 + r;
                float v = (gl >= 0 && gl < L) ? src[(size_t)ci * S * L + gl] : 0.0f;
                __half hi = __float2half_rn(v);
                __half lo = __float2half_rn(v - __half2float(hi));
                A_p[0][r * AST + ci] = hi;
                A_p[1][r * AST + ci] = lo;
            }
        }
        __syncthreads();

        // ---- HMMA: term(2) x tap(9) unrolled, kc = wid ----
        float acc[MT][NT][4];
#pragma unroll
        for (int mt = 0; mt < MT; ++mt)
#pragma unroll
            for (int nt = 0; nt < NT; ++nt)
#pragma unroll
                for (int e = 0; e < 4; ++e) acc[mt][nt][e] = 0.0f;

#pragma unroll
        for (int term = 0; term < 2; ++term) {
            const uint32_t aB = smA[term];
#pragma unroll
            for (int tap = 0; tap < KS; ++tap) {
                uint32_t bb[4];
                if constexpr (NT == 2) {
                    uint32_t addr = smB +
                        (uint32_t)(((tap * CO + lrow) * AST + kcb + lk) * 2);
                    ldsm4(addr, bb[0], bb[1], bb[2], bb[3]);
                } else {
                    uint32_t addr = smB +
                        (uint32_t)(((tap * CO + l2row) * AST + kcb + l2k) * 2);
                    ldsm2(addr, bb[0], bb[1]);
                }
#pragma unroll
                for (int mt = 0; mt < MT; ++mt) {
                    uint32_t a[4];
                    uint32_t addr = aB +
                        (uint32_t)(((mt * 16 + tap + lrow) * AST + kcb + lk) * 2);
                    ldsm4(addr, a[0], a[1], a[2], a[3]);
                    if constexpr (NT == 2) {
                        mma_f16(acc[mt][0], a, bb[0], bb[2]);
                        mma_f16(acc[mt][1], a, bb[1], bb[3]);
                    } else {
                        mma_f16(acc[mt][0], a, bb[0], bb[1]);
                    }
                }
            }
        }

        // ---- each warp writes its region; epilogue sums 8 regions ----
        const int row0 = lane >> 2;
        const int colb = (lane & 3) * 2;
#pragma unroll
        for (int mt = 0; mt < MT; ++mt)
#pragma unroll
            for (int nt = 0; nt < NT; ++nt) {
                float* p = stage + (size_t)(wid * M + mt * 16 + row0) * SST
                                 + nt * 8 + colb;
                p[0] = acc[mt][nt][0];  p[1] = acc[mt][nt][1];
                p[8*SST] = acc[mt][nt][2];  p[8*SST + 1] = acc[mt][nt][3];
            }
        __syncthreads();

        // ---- epilogue: out = x + relu( sum of 8 regions ) ----
        {
            const int m = tid & 63;
            const int g = tid >> 6;              // 4 groups
            constexpr int CPT = CO / 4;
#pragma unroll
            for (int c = 0; c < CPT; ++c) {
                const int co = g * CPT + c;
                float v = 0.0f;
#pragma unroll
                for (int r = 0; r < 8; ++r)
                    v += stage[(size_t)(r * M + m) * SST + co];
                float* p = base + ((size_t)(co0 + co) * S + s_cur) * L + l0 + m;
                *p = *p + fmaxf(v, 0.0f);
            }
        }

        // ---- per-batch grid barrier (release/acquire) ----
        __syncthreads();
        if (i < S - 1) {
            if (tid == 0) {
                red_rel_add1(ctr);
                const unsigned tgt = (unsigned)i * NB;
                while (ld_acq(ctr) < tgt) __nanosleep(16);
            }
            __syncthreads();
        }
    }
}

// ---------------------------------------------------------------------------
// Transpose [P, A, B] -> [P, B, A]
// ---------------------------------------------------------------------------
__global__ void transpose_kernel(const float* __restrict__ in,
                                 float* __restrict__ out, int A, int B)
{
    __shared__ float tile[32][33];
    const size_t p = blockIdx.z;
    const int b0 = blockIdx.x * 32;
    const int a0 = blockIdx.y * 32;
    const int tx = threadIdx.x, ty = threadIdx.y;
    const float* ip = in  + p * (size_t)A * B;
    float*       op = out + p * (size_t)A * B;
#pragma unroll
    for (int i = ty; i < 32; i += 8)
        tile[i][tx] = ip[(size_t)(a0+i)*B + (b0+tx)];
    __syncthreads();
#pragma unroll
    for (int i = ty; i < 32; i += 8)
        op[(size_t)(b0+i)*A + (a0+tx)] = tile[tx][i];
}

// Vertical: [B,C,S=H=128,L=W=256], CO=16. Horizontal (transposed): CO=8.
#define PASSV pass_kernel<128,256,16>
#define PASSH pass_kernel<256,128,8>

static constexpr int SMEM_V = 2*19584 + KS*16*136*2 + 8*64*17*4;  // 113152
static constexpr int SMEM_H = 2*19584 + KS* 8*136*2 + 8*64* 9*4;  // 77184

extern "C" void kernel_launch(void* const* d_in, const int* in_sizes, int n_in,
                              void* d_out, int out_size)
{
    const float* x    = (const float*)d_in[0];
    const float* w_ud = (const float*)d_in[1];
    const float* w_du = (const float*)d_in[2];
    const float* w_lr = (const float*)d_in[3];
    const float* w_rl = (const float*)d_in[4];
    float* buf = (float*)d_out;

    float* tbuf = nullptr;
    cudaGetSymbolAddress((void**)&tbuf, g_tmp);
    unsigned* ctr = nullptr;
    cudaGetSymbolAddress((void**)&ctr, g_ctrs);

    cudaFuncSetAttribute(PASSV, cudaFuncAttributeMaxDynamicSharedMemorySize, SMEM_V);
    cudaFuncSetAttribute(PASSH, cudaFuncAttributeMaxDynamicSharedMemorySize, SMEM_H);

    cudaMemsetAsync(ctr, 0, 4*BATCH*64*sizeof(unsigned), 0);
    cudaMemcpyAsync(buf, x, (size_t)NTOT * sizeof(float),
                    cudaMemcpyDeviceToDevice, 0);

    const unsigned PSTRIDE = BATCH * 64;

    // V: 4 l-tiles x 8 co-slices x 8 batches = 256 blocks (<=296 resident @occ2)
    dim3 gv(WW/64, CCH/16, BATCH);
    PASSV<<<gv, 256, SMEM_V>>>(buf, w_ud, ctr + 0*PSTRIDE, 0);
    PASSV<<<gv, 256, SMEM_V>>>(buf, w_du, ctr + 1*PSTRIDE, 1);

    transpose_kernel<<<dim3(WW/32, HH/32, BATCH*CCH), dim3(32,8)>>>(buf, tbuf, HH, WW);

    // H: 2 l-tiles x 16 co-slices x 8 batches = 256 blocks
    dim3 gh(HH/64, CCH/8, BATCH);
    PASSH<<<gh, 256, SMEM_H>>>(tbuf, w_lr, ctr + 2*PSTRIDE, 0);
    PASSH<<<gh, 256, SMEM_H>>>(tbuf, w_rl, ctr + 3*PSTRIDE, 1);

    transpose_kernel<<<dim3(HH/32, WW/32, BATCH*CCH), dim3(32,8)>>>(tbuf, buf, WW, HH);
}